// round 1
// baseline (speedup 1.0000x reference)
#include <cuda_runtime.h>

// Problem constants (fixed by this problem instance)
#define CTC_B 256
#define CTC_T 256
#define CTC_C 512
#define CTC_L 64
#define NSYM  65            // 64 label slots + 1 blank slot
#define NEGV  (-1e30f)

// Scratch (device globals: no allocation allowed in kernel_launch)
__device__ float g_emit[(size_t)CTC_B * CTC_T * NSYM];  // ~17 MB
__device__ float g_nll[CTC_B];

__device__ __forceinline__ float warpmax(float v) {
#pragma unroll
    for (int o = 16; o; o >>= 1) v = fmaxf(v, __shfl_xor_sync(0xffffffffu, v, o));
    return v;
}
__device__ __forceinline__ float warpsum(float v) {
#pragma unroll
    for (int o = 16; o; o >>= 1) v += __shfl_xor_sync(0xffffffffu, v, o);
    return v;
}

// Kernel 1: per (b,t) row: logsumexp over C=512, then write the 65 needed
// emission log-probs (64 label slots + blank) to g_emit.
// One warp per row; 8 warps (256 threads) per block.
__global__ void __launch_bounds__(256) lse_emit_kernel(
    const float* __restrict__ logits, const int* __restrict__ labels)
{
    __shared__ float srow[8][CTC_C];
    const int w    = threadIdx.x >> 5;
    const int lane = threadIdx.x & 31;
    const int row_id = blockIdx.x * 8 + w;          // = b*T + t

    const float4* row4 = (const float4*)(logits + (size_t)row_id * CTC_C);
    float4 v[4];
#pragma unroll
    for (int c = 0; c < 4; c++) v[c] = row4[c * 32 + lane];

    float mx = -3.4e38f;
#pragma unroll
    for (int c = 0; c < 4; c++)
        mx = fmaxf(mx, fmaxf(fmaxf(v[c].x, v[c].y), fmaxf(v[c].z, v[c].w)));
    mx = warpmax(mx);

    float s = 0.f;
#pragma unroll
    for (int c = 0; c < 4; c++)
        s += __expf(v[c].x - mx) + __expf(v[c].y - mx) +
             __expf(v[c].z - mx) + __expf(v[c].w - mx);
    s = warpsum(s);
    const float lse = mx + __logf(s);

    // Stash row in smem for the label gather
#pragma unroll
    for (int c = 0; c < 4; c++) {
        const int i4 = c * 32 + lane;
        srow[w][i4 * 4 + 0] = v[c].x;
        srow[w][i4 * 4 + 1] = v[c].y;
        srow[w][i4 * 4 + 2] = v[c].z;
        srow[w][i4 * 4 + 3] = v[c].w;
    }
    __syncwarp();

    const int b = row_id / CTC_T;
    const int* lab = labels + b * CTC_L;
    float* eout = g_emit + (size_t)row_id * NSYM;
#pragma unroll
    for (int i = lane; i < CTC_L; i += 32)
        eout[i] = srow[w][lab[i]] - lse;
    if (lane == 0)
        eout[CTC_L] = srow[w][CTC_C - 1] - lse;      // blank = last class
}

__device__ __forceinline__ float lae3(float x, float y, float z) {
    float m = fmaxf(fmaxf(x, y), z);
    float s = __expf(x - m) + __expf(y - m) + __expf(z - m);
    return m + __logf(s);
}

// Kernel 2: CTC forward DP. One warp per batch element.
// Lane l owns states s = 4l+j (j=0..3); lane 31 additionally owns s=128.
// Cross-lane deps (s-1, s-2 for j=0; s-2 for j=1) via two shfl_up per step.
__global__ void __launch_bounds__(32) ctc_dp_kernel(
    const int* __restrict__ labels,
    const int* __restrict__ label_length,
    const int* __restrict__ logit_length)
{
    const int b    = blockIdx.x;
    const int lane = threadIdx.x;
    const int* lab = labels + b * CTC_L;

    // Per-state metadata. s = 4*lane + j; parity(s) == parity(j).
    int  sym[5];
    bool skip1, skip3;   // only odd states can skip; j=1 -> k=2l, j=3 -> k=2l+1
#pragma unroll
    for (int j = 0; j < 5; j++) {
        const int s = 4 * lane + j;
        if (j & 1) sym[j] = s >> 1;     // (s-1)/2 for odd s
        else       sym[j] = CTC_L;      // blank slot
    }
    {
        const int s1 = 4 * lane + 1;
        const int k1 = s1 >> 1;
        const int k1m = (k1 > 0) ? k1 - 1 : 0;
        skip1 = (s1 >= 3) && (lab[k1] != lab[k1m]);
        const int k3 = (4 * lane + 3) >> 1;     // = 2*lane+1, k3-1 >= 0 always
        skip3 = (lab[k3] != lab[k3 - 1]);
    }

    const float* ebase = g_emit + (size_t)b * CTC_T * NSYM;

    // t = 0 init
    float e[5];
#pragma unroll
    for (int j = 0; j < 5; j++) e[j] = ebase[sym[j]];
    float a[5];
#pragma unroll
    for (int j = 0; j < 5; j++) {
        const int s = 4 * lane + j;
        a[j] = (s <= 1) ? e[j] : NEGV;
    }

    const int tl = logit_length[b];
    const int ll = label_length[b];

    float snap[5];
#pragma unroll
    for (int j = 0; j < 5; j++) snap[j] = a[j];     // valid if tl == 1

    for (int t = 1; t < CTC_T; t++) {
        const float* er = ebase + t * NSYM;
        float en[5];
#pragma unroll
        for (int j = 0; j < 5; j++) en[j] = __ldg(er + sym[j]);

        float am1 = __shfl_up_sync(0xffffffffu, a[3], 1);  // alpha[4l-1]
        float am2 = __shfl_up_sync(0xffffffffu, a[2], 1);  // alpha[4l-2]
        if (lane == 0) { am1 = NEGV; am2 = NEGV; }

        const float na0 = lae3(a[0], am1,  NEGV)                 + en[0];
        const float na1 = lae3(a[1], a[0], skip1 ? am1 : NEGV)   + en[1];
        const float na2 = lae3(a[2], a[1], NEGV)                 + en[2];
        const float na3 = lae3(a[3], a[2], skip3 ? a[1] : NEGV)  + en[3];
        const float na4 = lae3(a[4], a[3], NEGV)                 + en[4];
        a[0] = na0; a[1] = na1; a[2] = na2; a[3] = na3; a[4] = na4;

        if (t == tl - 1) {
#pragma unroll
            for (int j = 0; j < 5; j++) snap[j] = a[j];
        }
    }

    // Gather snap at s_end = 2*ll and s_end-1 via uniform shuffles.
    const int se = 2 * ll;
    const int sm = se - 1;
    const float t0 = __shfl_sync(0xffffffffu, snap[0], (se >> 2) & 31);
    const float t1 = __shfl_sync(0xffffffffu, snap[1], (se >> 2) & 31);
    const float t2 = __shfl_sync(0xffffffffu, snap[2], (se >> 2) & 31);
    const float t3 = __shfl_sync(0xffffffffu, snap[3], (se >> 2) & 31);
    const float t4 = __shfl_sync(0xffffffffu, snap[4], 31);
    const float u0 = __shfl_sync(0xffffffffu, snap[0], (sm >> 2) & 31);
    const float u1 = __shfl_sync(0xffffffffu, snap[1], (sm >> 2) & 31);
    const float u2 = __shfl_sync(0xffffffffu, snap[2], (sm >> 2) & 31);
    const float u3 = __shfl_sync(0xffffffffu, snap[3], (sm >> 2) & 31);

    if (lane == 0) {
        const int je = se & 3;
        const float v_end = (se >= 128) ? t4
                          : (je == 0 ? t0 : je == 1 ? t1 : je == 2 ? t2 : t3);
        const int jm = sm & 3;
        const float v_m1 = (jm == 0 ? u0 : jm == 1 ? u1 : jm == 2 ? u2 : u3);

        const float m = fmaxf(v_end, v_m1);
        const float nll = -(m + __logf(__expf(v_end - m) + __expf(v_m1 - m)));
        g_nll[b] = nll;
    }
}

// Kernel 3: deterministic tree reduction -> mean over batch.
__global__ void __launch_bounds__(256) reduce_kernel(float* __restrict__ out) {
    __shared__ float smem[CTC_B];
    const int i = threadIdx.x;
    smem[i] = g_nll[i];
    __syncthreads();
#pragma unroll
    for (int o = CTC_B / 2; o; o >>= 1) {
        if (i < o) smem[i] += smem[i + o];
        __syncthreads();
    }
    if (i == 0) out[0] = smem[0] * (1.0f / CTC_B);
}

extern "C" void kernel_launch(void* const* d_in, const int* in_sizes, int n_in,
                              void* d_out, int out_size)
{
    const float* logits       = (const float*)d_in[0];
    const int*   labels       = (const int*)d_in[1];
    const int*   label_length = (const int*)d_in[2];
    const int*   logit_length = (const int*)d_in[3];

    lse_emit_kernel<<<(CTC_B * CTC_T) / 8, 256>>>(logits, labels);
    ctc_dp_kernel<<<CTC_B, 32>>>(labels, label_length, logit_length);
    reduce_kernel<<<1, 256>>>((float*)d_out);
    (void)in_sizes; (void)n_in; (void)out_size;
}

// round 2
// speedup vs baseline: 2.4887x; 2.4887x over previous
#include <cuda_runtime.h>

// Problem constants
#define CTC_B 256
#define CTC_T 256
#define CTC_C 512
#define CTC_L 64
#define CHUNK 64
#define NCHUNK (CTC_T / CHUNK)
#define ROWF  66            // smem floats per emission row: 64 labels + blank + pad
#define NEGV  (-1e30f)
#define LOG2E 1.4426950408889634f
#define LN2   0.6931471805599453f

__device__ float g_nll[CTC_B];

__device__ __forceinline__ float warpmax(float v) {
#pragma unroll
    for (int o = 16; o; o >>= 1) v = fmaxf(v, __shfl_xor_sync(0xffffffffu, v, o));
    return v;
}
__device__ __forceinline__ float warpsum(float v) {
#pragma unroll
    for (int o = 16; o; o >>= 1) v += __shfl_xor_sync(0xffffffffu, v, o);
    return v;
}

// logaddexp in log2 domain: 1 EX2 + 1 LG2
__device__ __forceinline__ float lae2_2(float x, float y) {
    float m = fmaxf(x, y);
    float d = fminf(x, y) - m;
    return m + __log2f(1.0f + exp2f(d));
}
// 3-way logaddexp in log2 domain: 3 EX2 + 1 LG2
__device__ __forceinline__ float lae2_3(float x, float y, float z) {
    float m = fmaxf(fmaxf(x, y), z);
    float s = exp2f(x - m) + exp2f(y - m) + exp2f(z - m);
    return m + __log2f(s);
}

// One block per batch element, 288 threads = 9 warps.
// Warps 0..7: compute log-softmax emissions for a 64-timestep chunk into smem
//             (double-buffered). Warp 8: CTC forward DP on the previous chunk.
__global__ void __launch_bounds__(288) ctc_fused_kernel(
    const float* __restrict__ logits,
    const int* __restrict__ labels,
    const int* __restrict__ label_length,
    const int* __restrict__ logit_length)
{
    __shared__ float semit[2][CHUNK][ROWF];
    __shared__ int   slab[CTC_L];

    const int b    = blockIdx.x;
    const int tid  = threadIdx.x;
    const int wid  = tid >> 5;
    const int lane = tid & 31;

    if (tid < CTC_L) slab[tid] = labels[b * CTC_L + tid];
    __syncthreads();

    // ---- DP-warp persistent state ----
    float a[5], snap[5];
    bool skip1 = false, skip3 = false;
    int tl = CTC_T, ll = 1;
    if (wid == 8) {
        tl = logit_length[b];
        ll = label_length[b];
        // lane owns states s = 4*lane + j (j=0..3); lane 31 also s=128 (j=4).
        const int s1 = 4 * lane + 1;           // odd, sym = 2*lane
        skip1 = (s1 >= 3) && (slab[2 * lane] != slab[2 * lane - 1]);
        skip3 = (slab[2 * lane + 1] != slab[2 * lane]);
#pragma unroll
        for (int j = 0; j < 5; j++) { a[j] = NEGV; snap[j] = NEGV; }
    }

    const float* bl = logits + (size_t)b * CTC_T * CTC_C;

    for (int c = 0; c <= NCHUNK; c++) {
        // ---------- fill chunk c ----------
        if (c < NCHUNK && wid < 8) {
            float* ebuf0 = &semit[c & 1][0][0];
#pragma unroll 1
            for (int i = 0; i < CHUNK / 8; i++) {
                const int j = wid * (CHUNK / 8) + i;
                const float*  row  = bl + (size_t)(c * CHUNK + j) * CTC_C;
                const float4* row4 = (const float4*)row;
                float4 v[4];
#pragma unroll
                for (int k = 0; k < 4; k++) v[k] = row4[k * 32 + lane];

                float mx = -3.4e38f;
#pragma unroll
                for (int k = 0; k < 4; k++)
                    mx = fmaxf(mx, fmaxf(fmaxf(v[k].x, v[k].y), fmaxf(v[k].z, v[k].w)));
                mx = warpmax(mx);
                const float mx2 = mx * LOG2E;

                float s = 0.f;
#pragma unroll
                for (int k = 0; k < 4; k++)
                    s += exp2f(fmaf(v[k].x, LOG2E, -mx2)) + exp2f(fmaf(v[k].y, LOG2E, -mx2)) +
                         exp2f(fmaf(v[k].z, LOG2E, -mx2)) + exp2f(fmaf(v[k].w, LOG2E, -mx2));
                s = warpsum(s);
                const float lse2 = mx2 + __log2f(s);   // log2-sum-exp

                // Gather the 65 needed symbols (re-read row: L1 hits).
                float* erow = ebuf0 + j * ROWF;
#pragma unroll
                for (int q = lane; q < CTC_L; q += 32)
                    erow[q] = fmaf(__ldg(row + slab[q]), LOG2E, -lse2);
                if (lane == 0)
                    erow[CTC_L] = fmaf(__ldg(row + CTC_C - 1), LOG2E, -lse2);
            }
        }

        // ---------- DP on chunk c-1 ----------
        if (c >= 1 && wid == 8) {
            const int cb = (c - 1) & 1;
            const int t0c = (c - 1) * CHUNK;
#pragma unroll 1
            for (int j = 0; j < CHUNK; j++) {
                const int t = t0c + j;
                const float2 eo = *(const float2*)&semit[cb][j][2 * lane]; // syms 2l, 2l+1
                const float  eb = semit[cb][j][CTC_L];                     // blank

                if (t == 0) {
                    a[0] = (lane == 0) ? eb   : NEGV;   // s=0 (blank)
                    a[1] = (lane == 0) ? eo.x : NEGV;   // s=1 (label 0)
                    a[2] = NEGV; a[3] = NEGV; a[4] = NEGV;
                } else {
                    float am1 = __shfl_up_sync(0xffffffffu, a[3], 1);  // alpha[4l-1]
                    if (lane == 0) am1 = NEGV;
                    const float na0 = lae2_2(a[0], am1)                        + eb;
                    const float na1 = lae2_3(a[1], a[0], skip1 ? am1  : NEGV)  + eo.x;
                    const float na2 = lae2_2(a[2], a[1])                       + eb;
                    const float na3 = lae2_3(a[3], a[2], skip3 ? a[1] : NEGV)  + eo.y;
                    const float na4 = lae2_2(a[4], a[3])                       + eb;
                    a[0] = na0; a[1] = na1; a[2] = na2; a[3] = na3; a[4] = na4;
                }
                if (t == tl - 1) {
#pragma unroll
                    for (int q = 0; q < 5; q++) snap[q] = a[q];
                }
            }
        }
        __syncthreads();
    }

    // ---------- finalize (DP warp) ----------
    if (wid == 8) {
        const int se = 2 * ll;          // final blank state
        const int sm = se - 1;
        const float t0 = __shfl_sync(0xffffffffu, snap[0], (se >> 2) & 31);
        const float t1 = __shfl_sync(0xffffffffu, snap[1], (se >> 2) & 31);
        const float t2 = __shfl_sync(0xffffffffu, snap[2], (se >> 2) & 31);
        const float t3 = __shfl_sync(0xffffffffu, snap[3], (se >> 2) & 31);
        const float t4 = __shfl_sync(0xffffffffu, snap[4], 31);
        const float u0 = __shfl_sync(0xffffffffu, snap[0], (sm >> 2) & 31);
        const float u1 = __shfl_sync(0xffffffffu, snap[1], (sm >> 2) & 31);
        const float u2 = __shfl_sync(0xffffffffu, snap[2], (sm >> 2) & 31);
        const float u3 = __shfl_sync(0xffffffffu, snap[3], (sm >> 2) & 31);

        if (lane == 0) {
            const int je = se & 3;
            const float v_end = (se >= 4 * 32) ? t4
                              : (je == 0 ? t0 : je == 1 ? t1 : je == 2 ? t2 : t3);
            const int jm = sm & 3;
            const float v_m1 = (jm == 0 ? u0 : jm == 1 ? u1 : jm == 2 ? u2 : u3);
            g_nll[b] = -LN2 * lae2_2(v_end, v_m1);     // back to natural log
        }
    }
}

// Deterministic tree reduction -> mean over batch.
__global__ void __launch_bounds__(256) reduce_kernel(float* __restrict__ out) {
    __shared__ float smem[CTC_B];
    const int i = threadIdx.x;
    smem[i] = g_nll[i];
    __syncthreads();
#pragma unroll
    for (int o = CTC_B / 2; o; o >>= 1) {
        if (i < o) smem[i] += smem[i + o];
        __syncthreads();
    }
    if (i == 0) out[0] = smem[0] * (1.0f / CTC_B);
}

extern "C" void kernel_launch(void* const* d_in, const int* in_sizes, int n_in,
                              void* d_out, int out_size)
{
    const float* logits       = (const float*)d_in[0];
    const int*   labels       = (const int*)d_in[1];
    const int*   label_length = (const int*)d_in[2];
    const int*   logit_length = (const int*)d_in[3];

    ctc_fused_kernel<<<CTC_B, 288>>>(logits, labels, label_length, logit_length);
    reduce_kernel<<<1, 256>>>((float*)d_out);
    (void)in_sizes; (void)n_in; (void)out_size;
}